// round 2
// baseline (speedup 1.0000x reference)
#include <cuda_runtime.h>
#include <cstdint>

#define NB       16
#define CIN      256
#define COUT     256
#define HH       32
#define WWID     32
#define HWSZ     1024
#define KWSTRIDE 2304   // CIN * 9 (o-stride in weight)
#define PT       128    // positions per block tile
#define OT       64     // output channels per block tile
#define NTHREADS 256

// packed fp32x2 FMA (SASS FFMA2) — 2x fp32 throughput on sm_103a
__device__ __forceinline__ void ffma2(float2& d, float2 a, float2 b) {
    unsigned long long du = *reinterpret_cast<unsigned long long*>(&d);
    unsigned long long au = *reinterpret_cast<unsigned long long*>(&a);
    unsigned long long bu = *reinterpret_cast<unsigned long long*>(&b);
    asm("fma.rn.f32x2 %0, %1, %2, %0;" : "+l"(du) : "l"(au), "l"(bu));
    d = *reinterpret_cast<float2*>(&du);
}

__global__ __launch_bounds__(NTHREADS)
void deform_conv_kernel(const float* __restrict__ x,
                        const float* __restrict__ offset,
                        const float* __restrict__ weight,
                        float* __restrict__ out)
{
    // smem: 9216 + 18432 + 4096 + 9216 + 4608 = 45568 B (< 48KB static limit)
    __shared__ __align__(16) short4 s_idx[9][PT];     // 4 clipped corner indices
    __shared__ __align__(16) float4 s_w[9][PT];       // 4 corner weights (validity pre-folded)
    __shared__ __align__(16) float  s_x[HWSZ];        // current input channel
    __shared__ __align__(16) float2 s_wt[2][9][OT];   // W duplicated into pairs, double buffered
    __shared__ __align__(16) float  s_v[9][PT];       // deformed im2col slice for current c

    const int tid = threadIdx.x;
    const int n   = blockIdx.z;
    const int oc0 = blockIdx.y * OT;
    const int p0  = blockIdx.x * PT;

    // ---- build sampling tables (once per block) ----
    for (int j = tid; j < 9 * PT; j += NTHREADS) {
        const int k  = j >> 7;
        const int p  = j & (PT - 1);
        const int gp = p0 + p;
        const int yi = gp >> 5;
        const int xi = gp & 31;
        const float2 d2 = *reinterpret_cast<const float2*>(
            offset + ((size_t)n * HWSZ + gp) * 18 + 2 * k);
        const float py = (float)yi + (float)(k / 3 - 1) + d2.x;  // dy first
        const float px = (float)xi + (float)(k % 3 - 1) + d2.y;  // dx second
        const float y0 = floorf(py), x0 = floorf(px);
        const float ly = py - y0, lx = px - x0;
        const float hy = 1.f - ly, hx = 1.f - lx;
        const float vy0 = (y0 >= 0.f  && y0 <= 31.f) ? 1.f : 0.f;
        const float vy1 = (y0 >= -1.f && y0 <= 30.f) ? 1.f : 0.f;
        const float vx0 = (x0 >= 0.f  && x0 <= 31.f) ? 1.f : 0.f;
        const float vx1 = (x0 >= -1.f && x0 <= 30.f) ? 1.f : 0.f;
        const int iy0 = (int)fminf(fmaxf(y0,       0.f), 31.f);
        const int iy1 = (int)fminf(fmaxf(y0 + 1.f, 0.f), 31.f);
        const int ix0 = (int)fminf(fmaxf(x0,       0.f), 31.f);
        const int ix1 = (int)fminf(fmaxf(x0 + 1.f, 0.f), 31.f);
        s_idx[k][p] = make_short4((short)(iy0 * 32 + ix0), (short)(iy0 * 32 + ix1),
                                  (short)(iy1 * 32 + ix0), (short)(iy1 * 32 + ix1));
        s_w[k][p] = make_float4(hy * hx * vy0 * vx0, hy * lx * vy0 * vx1,
                                ly * hx * vy1 * vx0, ly * lx * vy1 * vx1);
    }

    // ---- per-thread W-prefetch metadata (fixed across c) ----
    const float* xbase = x + (size_t)n * CIN * HWSZ;
    int wkk[3], wol[3];
    bool wvalid[3];
    const float* wptr[3];
    #pragma unroll
    for (int r = 0; r < 3; ++r) {
        const int j = tid + r * NTHREADS;
        wvalid[r] = (j < 9 * OT);
        const int ol = wvalid[r] ? (j / 9) : 0;
        const int kk = wvalid[r] ? (j - ol * 9) : 0;
        wol[r] = ol; wkk[r] = kk;
        wptr[r] = weight + (size_t)(oc0 + ol) * KWSTRIDE + kk;
    }

    // ---- preload c = 0 ----
    {
        float4 xr = reinterpret_cast<const float4*>(xbase)[tid];
        reinterpret_cast<float4*>(s_x)[tid] = xr;
        #pragma unroll
        for (int r = 0; r < 3; ++r) {
            if (wvalid[r]) {
                const float wv = *wptr[r];
                s_wt[0][wkk[r]][wol[r]] = make_float2(wv, wv);
                wptr[r] += 9;
            }
        }
    }
    __syncthreads();

    const int to = tid >> 5;   // warp id -> o-subgroup (uniform within warp => broadcast LDS)
    const int tp = tid & 31;   // lane -> position group

    float2 acc[8][2];
    #pragma unroll
    for (int i = 0; i < 8; ++i) {
        acc[i][0] = make_float2(0.f, 0.f);
        acc[i][1] = make_float2(0.f, 0.f);
    }

    int buf = 0;
    for (int c = 0; c < CIN; ++c) {
        // prefetch c+1 into registers (hidden under V-build)
        float4 xr;
        float wr[3];
        const bool has = (c + 1 < CIN);
        if (has) {
            xr = reinterpret_cast<const float4*>(xbase + (size_t)(c + 1) * HWSZ)[tid];
            #pragma unroll
            for (int r = 0; r < 3; ++r)
                if (wvalid[r]) { wr[r] = *wptr[r]; wptr[r] += 9; }
        }

        // build deformed im2col slice V[k][p] for channel c
        for (int j = tid; j < 9 * PT; j += NTHREADS) {
            const int k = j >> 7;
            const int p = j & (PT - 1);
            const short4 id = s_idx[k][p];
            const float4 w  = s_w[k][p];
            s_v[k][p] = w.x * s_x[id.x] + w.y * s_x[id.y]
                      + w.z * s_x[id.z] + w.w * s_x[id.w];
        }
        __syncthreads();   // V ready; all reads of s_x done

        // stash prefetched data (s_x safe to overwrite now; W into other buffer)
        if (has) {
            reinterpret_cast<float4*>(s_x)[tid] = xr;
            #pragma unroll
            for (int r = 0; r < 3; ++r)
                if (wvalid[r])
                    s_wt[buf ^ 1][wkk[r]][wol[r]] = make_float2(wr[r], wr[r]);
        }

        // outer-product GEMM: acc[8 o][4 p] += W[o,c,k] * V[k,p]  (fp32x2)
        #pragma unroll
        for (int k = 0; k < 9; ++k) {
            const float4* wp =
                reinterpret_cast<const float4*>(&s_wt[buf][k][to * 8]);
            const float4 wA = wp[0], wB = wp[1], wC = wp[2], wD = wp[3];
            const float4 vv = *reinterpret_cast<const float4*>(&s_v[k][tp * 4]);
            const float2 v01 = make_float2(vv.x, vv.y);
            const float2 v23 = make_float2(vv.z, vv.w);
            const float2 w0 = make_float2(wA.x, wA.y), w1 = make_float2(wA.z, wA.w);
            const float2 w2 = make_float2(wB.x, wB.y), w3 = make_float2(wB.z, wB.w);
            const float2 w4 = make_float2(wC.x, wC.y), w5 = make_float2(wC.z, wC.w);
            const float2 w6 = make_float2(wD.x, wD.y), w7 = make_float2(wD.z, wD.w);
            ffma2(acc[0][0], w0, v01); ffma2(acc[0][1], w0, v23);
            ffma2(acc[1][0], w1, v01); ffma2(acc[1][1], w1, v23);
            ffma2(acc[2][0], w2, v01); ffma2(acc[2][1], w2, v23);
            ffma2(acc[3][0], w3, v01); ffma2(acc[3][1], w3, v23);
            ffma2(acc[4][0], w4, v01); ffma2(acc[4][1], w4, v23);
            ffma2(acc[5][0], w5, v01); ffma2(acc[5][1], w5, v23);
            ffma2(acc[6][0], w6, v01); ffma2(acc[6][1], w6, v23);
            ffma2(acc[7][0], w7, v01); ffma2(acc[7][1], w7, v23);
        }
        __syncthreads();   // protects s_v / s_x / s_wt for next iteration
        buf ^= 1;
    }

    // ---- epilogue: each thread owns 8 o-rows x 4 contiguous positions ----
    float* obase = out + ((size_t)n * COUT + oc0 + to * 8) * HWSZ + p0 + tp * 4;
    #pragma unroll
    for (int i = 0; i < 8; ++i) {
        const float4 r = make_float4(acc[i][0].x, acc[i][0].y,
                                     acc[i][1].x, acc[i][1].y);
        *reinterpret_cast<float4*>(obase + (size_t)i * HWSZ) = r;
    }
}

extern "C" void kernel_launch(void* const* d_in, const int* in_sizes, int n_in,
                              void* d_out, int out_size)
{
    const float* x      = (const float*)d_in[0];
    const float* offset = (const float*)d_in[1];
    const float* weight = (const float*)d_in[2];
    float* out          = (float*)d_out;

    dim3 grid(HWSZ / PT, COUT / OT, NB);   // 8 x 4 x 16 = 512 blocks
    deform_conv_kernel<<<grid, NTHREADS>>>(x, offset, weight, out);
}

// round 4
// speedup vs baseline: 3.5707x; 3.5707x over previous
#include <cuda_runtime.h>
#include <cuda_bf16.h>
#include <cstdint>

#define NB      16
#define CIN     256
#define COUT    256
#define HWSZ    1024
#define PT      128
#define NSTAGE  128          // 2 input channels per stage
#define NT      512          // 16 warps, 4(M) x 4(N)

// smem layout (bytes from dynamic base)
#define A_STRIDE 144                 // 64 bf16 + 8 pad (ldmatrix conflict-free)
#define A_SZ     (128 * A_STRIDE)    // 18432
#define B_STRIDE 528                 // 256 bf16 + 8 pad
#define B_SZ     (64 * B_STRIDE)     // 33792
#define X_SZ     8192                // float2[1024] channel-pair
#define A_OFF    0
#define B_OFF    (2 * A_SZ)          // 36864
#define X_OFF    (B_OFF + 2 * B_SZ)  // 104448
#define SMEM_DYN (X_OFF + 2 * X_SZ)  // 120832

// pre-split weights, k-major: [stage][64 k][256 o] bf16
__device__ __align__(16) __nv_bfloat16 g_wp[(size_t)NSTAGE * 64 * 256];

// ---------------- helpers ----------------
__device__ __forceinline__ uint32_t smem_u32(const void* p) {
    uint32_t a;
    asm("{ .reg .u64 t; cvta.to.shared.u64 t, %1; cvt.u32.u64 %0, t; }" : "=r"(a) : "l"(p));
    return a;
}
__device__ __forceinline__ void ldm_x4(uint32_t r[4], uint32_t a) {
    asm volatile("ldmatrix.sync.aligned.m8n8.x4.shared.b16 {%0,%1,%2,%3}, [%4];"
                 : "=r"(r[0]), "=r"(r[1]), "=r"(r[2]), "=r"(r[3]) : "r"(a));
}
__device__ __forceinline__ void ldm_x4_t(uint32_t r[4], uint32_t a) {
    asm volatile("ldmatrix.sync.aligned.m8n8.x4.trans.shared.b16 {%0,%1,%2,%3}, [%4];"
                 : "=r"(r[0]), "=r"(r[1]), "=r"(r[2]), "=r"(r[3]) : "r"(a));
}
__device__ __forceinline__ void mma16816(float d[4], const uint32_t a[4], const uint32_t b[2]) {
    asm volatile("mma.sync.aligned.m16n8k16.row.col.f32.bf16.bf16.f32 "
                 "{%0,%1,%2,%3},{%4,%5,%6,%7},{%8,%9},{%0,%1,%2,%3};"
                 : "+f"(d[0]), "+f"(d[1]), "+f"(d[2]), "+f"(d[3])
                 : "r"(a[0]), "r"(a[1]), "r"(a[2]), "r"(a[3]), "r"(b[0]), "r"(b[1]));
}

// ---------------- weight prep: split hi/lo, transpose to k-major ----------------
__global__ void prep_weights(const float* __restrict__ weight) {
    const int j = blockIdx.x * blockDim.x + threadIdx.x;
    if (j >= NSTAGE * 256) return;
    const int s = j >> 8, o = j & 255;
    __nv_bfloat16* dst = g_wp + (size_t)s * 64 * 256 + o;
    #pragma unroll
    for (int ch = 0; ch < 2; ++ch) {
        const float* ws = weight + (size_t)o * 2304 + (2 * s + ch) * 9;
        #pragma unroll
        for (int t = 0; t < 9; ++t) {
            const float wv = ws[t];
            const __nv_bfloat16 hi = __float2bfloat16(wv);
            const __nv_bfloat16 lo = __float2bfloat16(wv - __bfloat162float(hi));
            dst[(ch * 32 + t) * 256]      = hi;   // pairs with vhi
            dst[(ch * 32 + t + 9) * 256]  = hi;   // pairs with vlo
            dst[(ch * 32 + t + 18) * 256] = lo;   // pairs with vhi
        }
        #pragma unroll
        for (int t = 27; t < 32; ++t)
            dst[(ch * 32 + t) * 256] = __float2bfloat16(0.f);
    }
}

// ---------------- main kernel ----------------
__global__ __launch_bounds__(NT)
void dcn_mma_kernel(const float* __restrict__ x,
                    const float* __restrict__ offset,
                    float* __restrict__ out)
{
    extern __shared__ char sm[];
    const uint32_t sb = smem_u32(sm);

    const int tid  = threadIdx.x;
    const int wid  = tid >> 5, lane = tid & 31;
    const int n    = blockIdx.y;
    const int p0   = blockIdx.x * PT;
    const int warpM = wid & 3;     // 4 M-tiles of 32
    const int warpN = wid >> 2;    // 4 N-tiles of 64

    // zero A pad cols 27..31 / 59..63 of both buffers (never written again)
    if (tid < 256) {
        char* rp = sm + A_OFF + (tid >> 7) * A_SZ + (tid & 127) * A_STRIDE;
        #pragma unroll
        for (int i = 0; i < 5; ++i) {
            ((unsigned short*)(rp + 54))[i]  = 0;
            ((unsigned short*)(rp + 118))[i] = 0;
        }
    }

    // ---- sampling tables -> registers (3 entries/thread, 1152 total) ----
    uint32_t tlo[3], thi[3];
    float4 twt[3];
    #pragma unroll
    for (int e = 0; e < 3; ++e) {
        const int j = tid + e * NT;
        if (j < 9 * PT) {
            const int k = j >> 7, p = j & 127;
            const int gp = p0 + p;
            const float2 d2 = *reinterpret_cast<const float2*>(
                offset + ((size_t)n * HWSZ + gp) * 18 + 2 * k);
            const float py = (float)(gp >> 5) + (float)(k / 3 - 1) + d2.x;
            const float px = (float)(gp & 31) + (float)(k % 3 - 1) + d2.y;
            const float y0 = floorf(py), x0 = floorf(px);
            const float ly = py - y0, lx = px - x0;
            const float hy = 1.f - ly, hx = 1.f - lx;
            const float vy0 = (y0 >= 0.f && y0 <= 31.f) ? 1.f : 0.f;
            const float vy1 = (y0 >= -1.f && y0 <= 30.f) ? 1.f : 0.f;
            const float vx0 = (x0 >= 0.f && x0 <= 31.f) ? 1.f : 0.f;
            const float vx1 = (x0 >= -1.f && x0 <= 30.f) ? 1.f : 0.f;
            const uint32_t iy0 = (uint32_t)(int)fminf(fmaxf(y0, 0.f), 31.f);
            const uint32_t iy1 = (uint32_t)(int)fminf(fmaxf(y0 + 1.f, 0.f), 31.f);
            const uint32_t ix0 = (uint32_t)(int)fminf(fmaxf(x0, 0.f), 31.f);
            const uint32_t ix1 = (uint32_t)(int)fminf(fmaxf(x0 + 1.f, 0.f), 31.f);
            tlo[e] = (iy0 * 32 + ix0) | ((iy0 * 32 + ix1) << 16);
            thi[e] = (iy1 * 32 + ix0) | ((iy1 * 32 + ix1) << 16);
            twt[e] = make_float4(hy * hx * vy0 * vx0, hy * lx * vy0 * vx1,
                                 ly * hx * vy1 * vx0, ly * lx * vy1 * vx1);
        } else {
            tlo[e] = thi[e] = 0;
            twt[e] = make_float4(0.f, 0.f, 0.f, 0.f);
        }
    }

    const float* xn = x + (size_t)n * CIN * HWSZ;

    // ---- stage register prefetch / store ----
    uint4 br[4];
    float2 xa, xb;
    auto load_stage = [&](int st) {
        const uint4* gs = (const uint4*)(g_wp + (size_t)st * 64 * 256);
        #pragma unroll
        for (int q = 0; q < 4; ++q) br[q] = gs[tid + q * NT];   // 2048 uint4/stage
        xa = *(const float2*)(xn + (size_t)(2 * st) * HWSZ + 2 * tid);
        xb = *(const float2*)(xn + (size_t)(2 * st + 1) * HWSZ + 2 * tid);
    };
    auto store_stage = [&](int st) {
        char* bd = sm + B_OFF + (st & 1) * B_SZ;
        #pragma unroll
        for (int q = 0; q < 4; ++q) {
            const int idx = tid + q * NT;
            *(uint4*)(bd + (idx >> 5) * B_STRIDE + (idx & 31) * 16) = br[q];
        }
        float2* xd = (float2*)(sm + X_OFF + (st & 1) * X_SZ);
        xd[2 * tid]     = make_float2(xa.x, xb.x);
        xd[2 * tid + 1] = make_float2(xa.y, xb.y);
    };

    // ---- build deformed bf16-split A tile ----
    auto build_a = [&](int st) {
        const float2* xp = (const float2*)(sm + X_OFF + (st & 1) * X_SZ);
        char* abuf = sm + A_OFF + (st & 1) * A_SZ;
        #pragma unroll
        for (int e = 0; e < 3; ++e) {
            const int j = tid + e * NT;
            if (e == 2 && j >= 9 * PT) break;
            const int k = j >> 7, p = j & 127;
            const float2 c00 = xp[tlo[e] & 0xFFFF];
            const float2 c01 = xp[tlo[e] >> 16];
            const float2 c10 = xp[thi[e] & 0xFFFF];
            const float2 c11 = xp[thi[e] >> 16];
            const float4 w = twt[e];
            const float v0 = w.x * c00.x + w.y * c01.x + w.z * c10.x + w.w * c11.x;
            const float v1 = w.x * c00.y + w.y * c01.y + w.z * c10.y + w.w * c11.y;
            const __nv_bfloat16 h0 = __float2bfloat16(v0);
            const __nv_bfloat16 l0 = __float2bfloat16(v0 - __bfloat162float(h0));
            const __nv_bfloat16 h1 = __float2bfloat16(v1);
            const __nv_bfloat16 l1 = __float2bfloat16(v1 - __bfloat162float(h1));
            char* row = abuf + p * A_STRIDE;
            *(__nv_bfloat16*)(row + 2 * k)           = h0;
            *(__nv_bfloat16*)(row + 2 * k + 18)      = l0;
            *(__nv_bfloat16*)(row + 2 * k + 36)      = h0;
            *(__nv_bfloat16*)(row + 64 + 2 * k)      = h1;
            *(__nv_bfloat16*)(row + 64 + 2 * k + 18) = l1;
            *(__nv_bfloat16*)(row + 64 + 2 * k + 36) = h1;
        }
    };

    // ---- accumulators ----
    float acc[2][8][4];
    #pragma unroll
    for (int i = 0; i < 2; ++i)
        #pragma unroll
        for (int j = 0; j < 8; ++j)
            #pragma unroll
            for (int q = 0; q < 4; ++q) acc[i][j][q] = 0.f;

    // ldmatrix address components (constant across stages)
    const uint32_t aRowOff = (uint32_t)(warpM * 32 + (lane & 15)) * A_STRIDE
                           + (uint32_t)(lane >> 4) * 16;          // +8 cols (bytes)
    const uint32_t bRowOff = (uint32_t)(lane & 15) * B_STRIDE
                           + (uint32_t)(warpN * 128) + (uint32_t)(lane >> 4) * 16;

    auto mma_stage = [&](int st) {
        const uint32_t ab = sb + A_OFF + (st & 1) * A_SZ;
        const uint32_t bb = sb + B_OFF + (st & 1) * B_SZ;
        #pragma unroll
        for (int kc = 0; kc < 4; ++kc) {
            const uint32_t k0b = kc * 32;                 // 16 cols * 2B
            uint32_t a0[4], a1[4];
            ldm_x4(a0, ab + aRowOff + k0b);
            ldm_x4(a1, ab + aRowOff + 16 * A_STRIDE + k0b);
            #pragma unroll
            for (int jt = 0; jt < 4; ++jt) {
                uint32_t b[4];
                ldm_x4_t(b, bb + bRowOff + kc * 16 * B_STRIDE + jt * 32);
                mma16816(acc[0][2 * jt],     a0, b);
                mma16816(acc[0][2 * jt + 1], a0, b + 2);
                mma16816(acc[1][2 * jt],     a1, b);
                mma16816(acc[1][2 * jt + 1], a1, b + 2);
            }
        }
    };

    // ---- prologue ----
    load_stage(0);
    store_stage(0);
    __syncthreads();
    build_a(0);
    __syncthreads();

    // ---- main loop: prefetch(s+1) || MMA(s), then build(s+1) ----
    for (int s = 0; s < NSTAGE; ++s) {
        const bool more = (s + 1 < NSTAGE);
        if (more) load_stage(s + 1);
        mma_stage(s);
        if (more) {
            store_stage(s + 1);
            __syncthreads();
            build_a(s + 1);
        }
        __syncthreads();
    }

    // ---- epilogue: direct global stores ----
    const int pbase = p0 + warpM * 32 + (lane >> 2);
    const int obase = warpN * 64 + (lane & 3) * 2;
    float* ob = out + (size_t)n * COUT * HWSZ;
    #pragma unroll
    for (int mt = 0; mt < 2; ++mt) {
        #pragma unroll
        for (int j = 0; j < 8; ++j) {
            const int o = obase + j * 8;
            const int p = pbase + mt * 16;
            ob[(size_t)o * HWSZ + p]           = acc[mt][j][0];
            ob[(size_t)(o + 1) * HWSZ + p]     = acc[mt][j][1];
            ob[(size_t)o * HWSZ + p + 8]       = acc[mt][j][2];
            ob[(size_t)(o + 1) * HWSZ + p + 8] = acc[mt][j][3];
        }
    }
}

extern "C" void kernel_launch(void* const* d_in, const int* in_sizes, int n_in,
                              void* d_out, int out_size)
{
    const float* x      = (const float*)d_in[0];
    const float* offset = (const float*)d_in[1];
    const float* weight = (const float*)d_in[2];
    float* out          = (float*)d_out;

    static int smem_set = 0;
    if (!smem_set) {
        cudaFuncSetAttribute(dcn_mma_kernel,
                             cudaFuncAttributeMaxDynamicSharedMemorySize, SMEM_DYN);
        smem_set = 1;
    }

    prep_weights<<<(NSTAGE * 256 + 255) / 256, 256>>>(weight);
    dim3 grid(HWSZ / PT, NB);                 // 8 x 16 = 128 blocks, one wave
    dcn_mma_kernel<<<grid, NT, SMEM_DYN>>>(x, offset, out);
}